// round 1
// baseline (speedup 1.0000x reference)
#include <cuda_runtime.h>

// ---------------------------------------------------------------------------
// DecGreenNet_product_CP3 — algebraically collapsed:
//   out[i] = c + sum_h v[h] * tanh(x_i . Wx1[:,h] + bx1[h])
// where
//   s_br = (sum_n y_n h_n) @ Wq2_br + (sum_n y_n) * bq2_br   (branch linearity)
//   rhs[b,d,f] = sum_x s0[b,x] s1[d,x] s2[f,x]
//   v = Wx2 @ rhs ,  c = bx2 . rhs
// ---------------------------------------------------------------------------

#define PI_F 3.14159265358979323846f

// scratch (__device__ globals — no allocations allowed)
__device__ float g_part[3][64][132];   // [branch][block][j<128]=weighted-h partial, [128]=sum_y partial
__device__ float g_rhs[512];
__device__ float g_v[512];
__device__ float g_c;

__device__ __forceinline__ float tanh_fast(float x) {
    float y;
    asm("tanh.approx.f32 %0, %1;" : "=f"(y) : "f"(x));
    return y;
}

// ---------------------------------------------------------------------------
// Kernel A: per-branch, per-node-chunk partials of (sum_n y_n * tanh(q_n*w_j + b_j))
// grid (64, 3) x 128 threads; each block handles 128 nodes of one branch.
// Uses accurate tanhf: the branch sums can cancel, so keep their error tiny.
// ---------------------------------------------------------------------------
__global__ void kernelA(const float* __restrict__ q0, const float* __restrict__ q1,
                        const float* __restrict__ q2,
                        const float* __restrict__ w0, const float* __restrict__ w1,
                        const float* __restrict__ w2,
                        const float* __restrict__ c0, const float* __restrict__ c1,
                        const float* __restrict__ c2,
                        const float* __restrict__ eq)
{
    const int br = blockIdx.y;
    const float* qx = (br == 0) ? q0 : ((br == 1) ? q1 : q2);
    const float* W1 = (br == 0) ? w0 : ((br == 1) ? w1 : w2);
    const float* B1 = (br == 0) ? c0 : ((br == 1) ? c1 : c2);

    __shared__ float sq[128];
    __shared__ float sy[128];

    const int t  = threadIdx.x;
    const int n0 = blockIdx.x * 128;

    const float pe = PI_F * eq[0];
    const float q  = qx[n0 + t];          // DQ = 1
    const float y  = sinf(pe * q);
    sq[t] = q;
    sy[t] = y;
    __syncthreads();

    const float w = W1[t];                // Wq1 is [1,128] -> scalar per column
    const float b = B1[t];
    float acc = 0.f;
#pragma unroll 8
    for (int n = 0; n < 128; n++) {
        acc = fmaf(sy[n], tanhf(fmaf(sq[n], w, b)), acc);
    }
    g_part[br][blockIdx.x][t] = acc;

    if (t == 0) {
        float s = 0.f;
        for (int n = 0; n < 128; n++) s += sy[n];
        g_part[br][blockIdx.x][128] = s;
    }
}

// ---------------------------------------------------------------------------
// Kernel B: one block, 512 threads.
//  1) reduce partials -> wh[3][128], sumy[3]
//  2) s[br][j2] = sum_j wh[br][j]*Wq2[j,j2] + sumy[br]*bq2[j2]
//  3) rhs[k] (k -> b,d,f) = sum_x s0[b,x] s1[d,x] s2[f,x] ; c = bx2 . rhs
// ---------------------------------------------------------------------------
__global__ void kernelB(const float* __restrict__ Wq02, const float* __restrict__ bq02,
                        const float* __restrict__ Wq12, const float* __restrict__ bq12,
                        const float* __restrict__ Wq22, const float* __restrict__ bq22,
                        const float* __restrict__ bx2)
{
    __shared__ float wh[3][128];
    __shared__ float sumy[3];
    __shared__ float s_sh[3][128];
    __shared__ float red[512];

    const int t = threadIdx.x;

    if (t < 384) {
        const int br = t >> 7, j = t & 127;
        float a = 0.f;
        for (int blk = 0; blk < 64; blk++) a += g_part[br][blk][j];
        wh[br][j] = a;
    } else if (t < 387) {
        const int br = t - 384;
        float s = 0.f;
        for (int blk = 0; blk < 64; blk++) s += g_part[br][blk][128];
        sumy[br] = s;
    }
    __syncthreads();

    if (t < 384) {
        const int br = t >> 7, j2 = t & 127;
        const float* W2 = (br == 0) ? Wq02 : ((br == 1) ? Wq12 : Wq22);
        const float* B2 = (br == 0) ? bq02 : ((br == 1) ? bq12 : bq22);
        float a = sumy[br] * B2[j2];
#pragma unroll 4
        for (int j = 0; j < 128; j++) a = fmaf(wh[br][j], W2[j * 128 + j2], a);
        s_sh[br][j2] = a;   // j2 = b*16 + x  (reshape [8,16])
    }
    __syncthreads();

    const int k = t;
    const int b = k >> 6, d = (k >> 3) & 7, f = k & 7;
    float r = 0.f;
#pragma unroll
    for (int x = 0; x < 16; x++)
        r += s_sh[0][b * 16 + x] * s_sh[1][d * 16 + x] * s_sh[2][f * 16 + x];
    g_rhs[k] = r;

    red[t] = bx2[k] * r;
    __syncthreads();
    for (int off = 256; off > 0; off >>= 1) {
        if (t < off) red[t] += red[t + off];
        __syncthreads();
    }
    if (t == 0) g_c = red[0];
}

// ---------------------------------------------------------------------------
// Kernel V: v[h] = sum_k Wx2[h,k] * rhs[k].  grid 64 x 256; one warp per row h.
// ---------------------------------------------------------------------------
__global__ void kernelV(const float* __restrict__ Wx2)
{
    const int h    = blockIdx.x * 8 + (threadIdx.x >> 5);
    const int lane = threadIdx.x & 31;
    const float* row = Wx2 + h * 512;
    float a = 0.f;
#pragma unroll 4
    for (int k = lane; k < 512; k += 32) a = fmaf(row[k], g_rhs[k], a);
#pragma unroll
    for (int o = 16; o; o >>= 1) a += __shfl_xor_sync(0xffffffffu, a, o);
    if (lane == 0) g_v[h] = a;
}

// ---------------------------------------------------------------------------
// Kernel C: main batch.  out[i] = c + sum_h v[h] * tanh(x_i . Wx1[:,h] + bx1[h])
// 256 threads/block, 1 row per thread. MUFU tanh.approx; FMA+MUFU co-limited.
// ---------------------------------------------------------------------------
__global__ void __launch_bounds__(256) kernelC(const float* __restrict__ X,
                                               const float* __restrict__ Wx1,
                                               const float* __restrict__ bx1,
                                               float* __restrict__ out, int Bn)
{
    __shared__ float4 wt[512];   // {Wx1[0,h], Wx1[1,h], Wx1[2,h], bx1[h]}
    __shared__ float  vs[512];

    const int t = threadIdx.x;
    for (int h = t; h < 512; h += 256) {
        wt[h] = make_float4(Wx1[h], Wx1[512 + h], Wx1[1024 + h], bx1[h]);
        vs[h] = g_v[h];
    }
    __syncthreads();

    const int i = blockIdx.x * 256 + t;
    if (i >= Bn) return;

    const float x0 = X[i * 3 + 0];
    const float x1 = X[i * 3 + 1];
    const float x2 = X[i * 3 + 2];

    float acc = g_c;
#pragma unroll 8
    for (int h = 0; h < 512; h++) {
        const float4 w = wt[h];
        const float a = fmaf(x2, w.z, fmaf(x1, w.y, fmaf(x0, w.x, w.w)));
        acc = fmaf(vs[h], tanh_fast(a), acc);
    }
    out[i] = acc;
}

// ---------------------------------------------------------------------------
extern "C" void kernel_launch(void* const* d_in, const int* in_sizes, int n_in,
                              void* d_out, int out_size)
{
    const float* input = (const float*)d_in[0];
    const float* eq    = (const float*)d_in[1];
    const float* q0    = (const float*)d_in[2];
    const float* q1    = (const float*)d_in[3];
    const float* q2    = (const float*)d_in[4];
    const float* Wx1   = (const float*)d_in[5];
    const float* bx1   = (const float*)d_in[6];
    const float* Wx2   = (const float*)d_in[7];
    const float* bx2   = (const float*)d_in[8];
    const float* Wq01  = (const float*)d_in[9];
    const float* bq01  = (const float*)d_in[10];
    const float* Wq02  = (const float*)d_in[11];
    const float* bq02  = (const float*)d_in[12];
    const float* Wq11  = (const float*)d_in[13];
    const float* bq11  = (const float*)d_in[14];
    const float* Wq12  = (const float*)d_in[15];
    const float* bq12  = (const float*)d_in[16];
    const float* Wq21  = (const float*)d_in[17];
    const float* bq21  = (const float*)d_in[18];
    const float* Wq22  = (const float*)d_in[19];
    const float* bq22  = (const float*)d_in[20];

    const int N  = in_sizes[2];          // 8192 quad nodes (DQ=1)
    const int Bn = in_sizes[0] / 3;      // 65536 rows (DIN=3)
    const int nblkA = N / 128;           // 64

    kernelA<<<dim3(nblkA, 3), 128>>>(q0, q1, q2,
                                     Wq01, Wq11, Wq21,
                                     bq01, bq11, bq21, eq);
    kernelB<<<1, 512>>>(Wq02, bq02, Wq12, bq12, Wq22, bq22, bx2);
    kernelV<<<64, 256>>>(Wx2);
    kernelC<<<(Bn + 255) / 256, 256>>>(input, Wx1, bx1, (float*)d_out, Bn);
}

// round 2
// speedup vs baseline: 1.1332x; 1.1332x over previous
#include <cuda_runtime.h>

// ---------------------------------------------------------------------------
// DecGreenNet_product_CP3 — algebraically collapsed:
//   out[i] = c + sum_h v[h] * tanh(x_i . Wx1[:,h] + bx1[h])
//   s_br = (sum_n y_n h_n) @ Wq2_br + (sum_n y_n) * bq2_br
//   rhs[b,d,f] = sum_x s0[b,x] s1[d,x] s2[f,x];  v = Wx2 @ rhs;  c = bx2 . rhs
// ---------------------------------------------------------------------------

#define PI_F 3.14159265358979323846f

__device__ float g_part[3][64][128];   // per-branch per-block weighted-tanh sums
__device__ float g_party[3][64];       // per-branch per-block sum of y
__device__ float g_rhs[512];
__device__ float g_v[512];
__device__ float g_c;

__device__ __forceinline__ float tanh_mufu(float x) {
    float y;
    asm("tanh.approx.f32 %0, %1;" : "=f"(y) : "f"(x));
    return y;
}

// accurate-enough tanh (~1e-6 abs err) built from 2 MUFU ops — used on the
// branch path where 8192-term sums could amplify tanh.approx's 1.5e-4 error.
__device__ __forceinline__ float tanh_acc(float z) {
    float e = __expf(2.0f * z);            // MUFU ex2
    return 1.0f - __fdividef(2.0f, e + 1.0f);  // MUFU rcp + fma
}

// ---------------------------------------------------------------------------
// Kernel A: branch partials.  grid (64, 3) x 256 threads.
// thread (j = t&127, half = t>>7) accumulates 64 nodes; halves reduced in smem.
// ---------------------------------------------------------------------------
__global__ void __launch_bounds__(256) kernelA(
        const float* __restrict__ q0, const float* __restrict__ q1,
        const float* __restrict__ q2,
        const float* __restrict__ w0, const float* __restrict__ w1,
        const float* __restrict__ w2,
        const float* __restrict__ c0, const float* __restrict__ c1,
        const float* __restrict__ c2,
        const float* __restrict__ eq)
{
    const int br = blockIdx.y;
    const float* qx = (br == 0) ? q0 : ((br == 1) ? q1 : q2);
    const float* W1 = (br == 0) ? w0 : ((br == 1) ? w1 : w2);
    const float* B1 = (br == 0) ? c0 : ((br == 1) ? c1 : c2);

    __shared__ float sq[128];
    __shared__ float sy[128];
    __shared__ float pacc[128];

    const int t    = threadIdx.x;
    const int j    = t & 127;
    const int half = t >> 7;

    if (t < 128) {
        const float pe = PI_F * eq[0];
        const float q  = qx[blockIdx.x * 128 + t];
        sq[t] = q;
        sy[t] = sinf(pe * q);
    }
    __syncthreads();

    const float w = W1[j];
    const float b = B1[j];
    const int   n0 = half * 64;
    float acc = 0.f;
#pragma unroll 8
    for (int n = n0; n < n0 + 64; n++) {
        acc = fmaf(sy[n], tanh_acc(fmaf(sq[n], w, b)), acc);
    }

    if (half == 1) pacc[j] = acc;
    __syncthreads();
    if (half == 0) g_part[br][blockIdx.x][j] = acc + pacc[j];

    if (t == 0) {
        float s = 0.f;
#pragma unroll 8
        for (int n = 0; n < 128; n++) s += sy[n];
        g_party[br][blockIdx.x] = s;
    }
}

// ---------------------------------------------------------------------------
// Kernel B: one block, 512 threads.  reduce partials -> s[br] -> rhs, c.
// ---------------------------------------------------------------------------
__global__ void kernelB(const float* __restrict__ Wq02, const float* __restrict__ bq02,
                        const float* __restrict__ Wq12, const float* __restrict__ bq12,
                        const float* __restrict__ Wq22, const float* __restrict__ bq22,
                        const float* __restrict__ bx2)
{
    __shared__ float wh[3][128];
    __shared__ float sumy[3];
    __shared__ float s_sh[3][128];
    __shared__ float red[512];

    const int t = threadIdx.x;

    if (t < 384) {
        const int br = t >> 7, j = t & 127;
        float a = 0.f;
#pragma unroll 8
        for (int blk = 0; blk < 64; blk++) a += g_part[br][blk][j];
        wh[br][j] = a;
    } else if (t < 387) {
        const int br = t - 384;
        float s = 0.f;
#pragma unroll 8
        for (int blk = 0; blk < 64; blk++) s += g_party[br][blk];
        sumy[br] = s;
    }
    __syncthreads();

    if (t < 384) {
        const int br = t >> 7, j2 = t & 127;
        const float* W2 = (br == 0) ? Wq02 : ((br == 1) ? Wq12 : Wq22);
        const float* B2 = (br == 0) ? bq02 : ((br == 1) ? bq12 : bq22);
        float a = sumy[br] * B2[j2];
#pragma unroll 8
        for (int j = 0; j < 128; j++) a = fmaf(wh[br][j], W2[j * 128 + j2], a);
        s_sh[br][j2] = a;                  // j2 = b*16 + x
    }
    __syncthreads();

    const int k = t;
    const int b = k >> 6, d = (k >> 3) & 7, f = k & 7;
    float r = 0.f;
#pragma unroll
    for (int x = 0; x < 16; x++)
        r += s_sh[0][b * 16 + x] * s_sh[1][d * 16 + x] * s_sh[2][f * 16 + x];
    g_rhs[k] = r;

    red[t] = bx2[k] * r;
    __syncthreads();
    for (int off = 256; off > 0; off >>= 1) {
        if (t < off) red[t] += red[t + off];
        __syncthreads();
    }
    if (t == 0) g_c = red[0];
}

// ---------------------------------------------------------------------------
// Kernel V: v[h] = Wx2[h,:] . rhs.  grid 64 x 256; warp per row, float4 loads.
// ---------------------------------------------------------------------------
__global__ void __launch_bounds__(256) kernelV(const float* __restrict__ Wx2)
{
    __shared__ float4 rsh[128];
    const int t = threadIdx.x;
    if (t < 128) rsh[t] = ((const float4*)g_rhs)[t];
    __syncthreads();

    const int h    = blockIdx.x * 8 + (t >> 5);
    const int lane = t & 31;
    const float4* row4 = (const float4*)(Wx2 + h * 512);
    float a = 0.f;
#pragma unroll
    for (int k = lane; k < 128; k += 32) {
        const float4 w = row4[k];
        const float4 r = rsh[k];
        a = fmaf(w.x, r.x, fmaf(w.y, r.y, fmaf(w.z, r.z, fmaf(w.w, r.w, a))));
    }
#pragma unroll
    for (int o = 16; o; o >>= 1) a += __shfl_xor_sync(0xffffffffu, a, o);
    if (lane == 0) g_v[h] = a;
}

// ---------------------------------------------------------------------------
// Kernel C: main batch.  512 threads = 128 rows x 4 h-quarters.
// Each thread: 128 iterations of (dot3 + tanh.approx + weighted acc).
// grid = Bn/128 = 512 blocks -> 8192 warps -> ~86% occupancy.
// ---------------------------------------------------------------------------
__global__ void __launch_bounds__(512) kernelC(const float* __restrict__ X,
                                               const float* __restrict__ Wx1,
                                               const float* __restrict__ bx1,
                                               float* __restrict__ out, int Bn)
{
    __shared__ float4 wt[512];   // {Wx1[0,h], Wx1[1,h], Wx1[2,h], bx1[h]}
    __shared__ float  vs[512];
    __shared__ float  part[3][128];

    const int t = threadIdx.x;
    wt[t] = make_float4(Wx1[t], Wx1[512 + t], Wx1[1024 + t], bx1[t]);
    vs[t] = g_v[t];
    __syncthreads();

    const int row = t & 127;
    const int hq  = t >> 7;           // 0..3
    const int h0  = hq << 7;
    const int i   = blockIdx.x * 128 + row;

    float x0 = 0.f, x1 = 0.f, x2 = 0.f;
    if (i < Bn) {
        x0 = X[i * 3 + 0];
        x1 = X[i * 3 + 1];
        x2 = X[i * 3 + 2];
    }

    float acc = 0.f;
#pragma unroll 8
    for (int hh = 0; hh < 128; hh++) {
        const float4 w = wt[h0 + hh];
        const float a = fmaf(x2, w.z, fmaf(x1, w.y, fmaf(x0, w.x, w.w)));
        acc = fmaf(vs[h0 + hh], tanh_mufu(a), acc);
    }

    if (hq > 0) part[hq - 1][row] = acc;
    __syncthreads();
    if (hq == 0 && i < Bn)
        out[i] = g_c + acc + part[0][row] + part[1][row] + part[2][row];
}

// ---------------------------------------------------------------------------
extern "C" void kernel_launch(void* const* d_in, const int* in_sizes, int n_in,
                              void* d_out, int out_size)
{
    const float* input = (const float*)d_in[0];
    const float* eq    = (const float*)d_in[1];
    const float* q0    = (const float*)d_in[2];
    const float* q1    = (const float*)d_in[3];
    const float* q2    = (const float*)d_in[4];
    const float* Wx1   = (const float*)d_in[5];
    const float* bx1   = (const float*)d_in[6];
    const float* Wx2   = (const float*)d_in[7];
    const float* bx2   = (const float*)d_in[8];
    const float* Wq01  = (const float*)d_in[9];
    const float* bq01  = (const float*)d_in[10];
    const float* Wq02  = (const float*)d_in[11];
    const float* bq02  = (const float*)d_in[12];
    const float* Wq11  = (const float*)d_in[13];
    const float* bq11  = (const float*)d_in[14];
    const float* Wq12  = (const float*)d_in[15];
    const float* bq12  = (const float*)d_in[16];
    const float* Wq21  = (const float*)d_in[17];
    const float* bq21  = (const float*)d_in[18];
    const float* Wq22  = (const float*)d_in[19];
    const float* bq22  = (const float*)d_in[20];

    const int N  = in_sizes[2];          // 8192 quad nodes
    const int Bn = in_sizes[0] / 3;      // 65536 rows
    const int nblkA = N / 128;           // 64

    kernelA<<<dim3(nblkA, 3), 256>>>(q0, q1, q2,
                                     Wq01, Wq11, Wq21,
                                     bq01, bq11, bq21, eq);
    kernelB<<<1, 512>>>(Wq02, bq02, Wq12, bq12, Wq22, bq22, bx2);
    kernelV<<<64, 256>>>(Wx2);
    kernelC<<<(Bn + 127) / 128, 512>>>(input, Wx1, bx1, (float*)d_out, Bn);
}